// round 13
// baseline (speedup 1.0000x reference)
#include <cuda_runtime.h>
#include <math.h>
#include <stdint.h>

#define KC       10
#define BT       256
#define NC       1152
#define ICC      8
#define OC       16
#define BTILE    2
#define NTHREADS 512
#define NWARP    16
#define CSZ      8            // cluster size (b-tiles sharing k share W[k])
#define TILES    9            // 1152 rows / 128
#define TROWS    128
#define ROWB     576          // padded SMEM row stride: 576B = 144 fl == 16 banks shift -> dense LDS
#define TILE_SMEM (TROWS * ROWB)   // 73728 B per buffer
#define TILE_GB  65536        // real bytes per tile (128 rows x 512 B)
#define SLICE_ROWS (TROWS / CSZ)   // 16 rows per rank

struct SmemLayout {
    float sred[NWARP][BTILE][OC];
    float zred[NWARP][BTILE];
    alignas(16) float vsum[BTILE][OC];
};

// ---- PTX helpers ----
__device__ __forceinline__ uint32_t s2u(const void* p) {
    uint32_t a;
    asm("{.reg .u64 t; cvta.to.shared.u64 t, %1; cvt.u32.u64 %0, t;}" : "=r"(a) : "l"(p));
    return a;
}
__device__ __forceinline__ void mbar_init(uint32_t a, uint32_t cnt) {
    asm volatile("mbarrier.init.shared.b64 [%0], %1;" :: "r"(a), "r"(cnt) : "memory");
}
__device__ __forceinline__ void mbar_expect_tx(uint32_t a, uint32_t bytes) {
    asm volatile("mbarrier.arrive.expect_tx.shared.b64 _, [%0], %1;" :: "r"(a), "r"(bytes) : "memory");
}
__device__ __forceinline__ void mbar_wait(uint32_t a, uint32_t phase) {
    asm volatile(
        "{\n\t.reg .pred P;\n\t"
        "WL_%=:\n\t"
        "mbarrier.try_wait.parity.acquire.cta.shared::cta.b64 P, [%0], %1, 0x989680;\n\t"
        "@P bra.uni WD_%=;\n\t"
        "bra.uni WL_%=;\n\t"
        "WD_%=:\n\t}"
        :: "r"(a), "r"(phase) : "memory");
}
__device__ __forceinline__ void mbar_arrive_cluster(uint32_t local_addr, uint32_t peer) {
    asm volatile(
        "{.reg .b32 ra; mapa.shared::cluster.u32 ra, %0, %1;"
        " mbarrier.arrive.shared::cluster.b64 _, [ra];}"
        :: "r"(local_addr), "r"(peer) : "memory");
}
__device__ __forceinline__ void cluster_sync_() {
    asm volatile("barrier.cluster.arrive.aligned;" ::: "memory");
    asm volatile("barrier.cluster.wait.aligned;" ::: "memory");
}
// 1D bulk copy global->shared, multicast to all cluster CTAs, tx to each dest's mbar.
__device__ __forceinline__ void bulk_mc(uint32_t dst, const void* src, uint32_t bytes,
                                        uint32_t mbar, uint16_t mask) {
    asm volatile(
        "cp.async.bulk.shared::cluster.global.mbarrier::complete_tx::bytes.multicast::cluster"
        " [%0], [%1], %2, [%3], %4;"
        :: "r"(dst), "l"(src), "r"(bytes), "r"(mbar), "h"(mask) : "memory");
}

// Rank's slice of tile: 16 rows, each 512 B, into padded (576 B stride) SMEM rows.
__device__ __forceinline__ void issue_tile(const char* Wk, int tile, uint32_t dstbase,
                                           uint32_t mbar, int rank) {
    const char* src = Wk + (size_t)tile * TILE_GB + (size_t)rank * SLICE_ROWS * 512;
    uint32_t dst = dstbase + (uint32_t)(rank * SLICE_ROWS) * ROWB;
    #pragma unroll
    for (int rr = 0; rr < SLICE_ROWS; rr++)
        bulk_mc(dst + rr * ROWB, src + rr * 512, 512, mbar, (uint16_t)0xFF);
}

// ---- reductions (identical to R10, proven) ----
__device__ __forceinline__ float reduce8q(const float a[8], int lane, int* Lp) {
    const bool s1 = lane & 4, s2 = lane & 8, s3 = lane & 16;
    float t4[4], t2[2], r;
    #pragma unroll
    for (int j = 0; j < 4; j++) {
        const float send = s1 ? a[j]     : a[4 + j];
        const float keep = s1 ? a[4 + j] : a[j];
        t4[j] = keep + __shfl_xor_sync(0xffffffffu, send, 4);
    }
    #pragma unroll
    for (int j = 0; j < 2; j++) {
        const float send = s2 ? t4[j]     : t4[2 + j];
        const float keep = s2 ? t4[2 + j] : t4[j];
        t2[j] = keep + __shfl_xor_sync(0xffffffffu, send, 8);
    }
    {
        const float send = s3 ? t2[0] : t2[1];
        const float keep = s3 ? t2[1] : t2[0];
        r = keep + __shfl_xor_sync(0xffffffffu, send, 16);
    }
    *Lp = (s1 ? 4 : 0) | (s2 ? 2 : 0) | (s3 ? 1 : 0);
    return r;
}
__device__ __forceinline__ void store_sred(SmemLayout* sm, int w, int oq, int L, float v) {
    sm->sred[w][L >> 2][4 * oq + (L & 3)] = v;
}
__device__ __forceinline__ void store_zred(SmemLayout* sm, int w, int lane,
                                           float z0, float z1) {
    const float send = (lane & 1) ? z0 : z1;
    const float keep = (lane & 1) ? z1 : z0;
    float zz = keep + __shfl_xor_sync(0xffffffffu, send, 1);
    #pragma unroll
    for (int sft = 2; sft <= 16; sft <<= 1)
        zz += __shfl_xor_sync(0xffffffffu, zz, sft);
    if (lane < 2) sm->zred[w][lane] = 0.25f * zz;   // c replicated over 4 oq-lanes
}
__device__ __forceinline__ void squash_stage(SmemLayout* sm, int t, bool uniform,
                                             bool first, bool writeOut,
                                             float* out, int k, int b0) {
    if (t < 32) {
        const int b = t >> 4, o = t & 15;
        float s = 0.f;
        #pragma unroll
        for (int w = 0; w < NWARP; w++) s += sm->sred[w][b][o];
        float Z;
        if (uniform) {
            Z = (float)NC;
        } else {
            Z = 0.f;
            #pragma unroll
            for (int w = 0; w < NWARP; w++) Z += sm->zred[w][b];
        }
        s /= Z;
        float sq = s * s;
        #pragma unroll
        for (int sft = 1; sft < 16; sft <<= 1)
            sq += __shfl_xor_sync(0xffffffffu, sq, sft);
        const float v = s * sqrtf(sq) / (1.0f + sq);   // squash
        sm->vsum[b][o] = first ? v : (sm->vsum[b][o] + v);
        if (writeOut) out[((size_t)k * BT + b0 + b) * OC + o] = v;
    }
    __syncthreads();
}

__global__ __launch_bounds__(NTHREADS, 1) __cluster_dims__(CSZ, 1, 1)
void caps_routing_kernel(const float* __restrict__ u, const float* __restrict__ W,
                         float* __restrict__ out) {
    extern __shared__ __align__(16) char wbuf[];     // 2 x TILE_SMEM
    __shared__ SmemLayout sm;
    __shared__ __align__(8) unsigned long long mbar[4];  // full0,full1,empty0,empty1

    const int k    = blockIdx.y;
    const int b0   = blockIdx.x * BTILE;
    const int t    = threadIdx.x;
    const int lane = t & 31, w = t >> 5;
    const int oq   = t & 3;              // comps [4oq, 4oq+4)
    const int r    = t >> 2;             // 0..127 -> local row within each tile

    uint32_t rank;
    asm("mov.u32 %0, %%cluster_ctarank;" : "=r"(rank));
    const uint32_t mb    = s2u(mbar);
    const uint32_t wb    = s2u(wbuf);
    const uint32_t fullA[2]  = {mb, mb + 8};
    const uint32_t emptyA[2] = {mb + 16, mb + 24};

    if (t == 0) {
        mbar_init(fullA[0], 1);  mbar_init(fullA[1], 1);
        mbar_init(emptyA[0], CSZ); mbar_init(emptyA[1], CSZ);
    }
    __syncthreads();
    cluster_sync_();                     // barriers visible before any multicast

    const char* Wk = (const char*)(W + (size_t)k * NC * ICC * OC);
    if (t == 0) {
        mbar_expect_tx(fullA[0], TILE_GB); issue_tile(Wk, 0, wb,             fullA[0], rank);
        mbar_expect_tx(fullA[1], TILE_GB); issue_tile(Wk, 1, wb + TILE_SMEM, fullA[1], rank);
    }

    // ---- Phase 1: pipelined tiles; u_hat into registers; fuse iter-0 s-sum ----
    float4 uh[BTILE][TILES];
    const float* ub0 = u + (size_t)b0 * NC * ICC;
    const float* ub1 = ub0 + (size_t)NC * ICC;
    float4 s0 = make_float4(0.f,0.f,0.f,0.f), s1 = make_float4(0.f,0.f,0.f,0.f);

    #pragma unroll
    for (int tile = 0; tile < TILES; tile++) {
        const int bsel = tile & 1;
        mbar_wait(fullA[bsel], (tile >> 1) & 1);       // acquire: LDS sees TMA data

        const int n = tile * TROWS + r;
        const float4 p0 = *(const float4*)(ub0 + (size_t)n * ICC);
        const float4 p1 = *(const float4*)(ub0 + (size_t)n * ICC + 4);
        const float4 q0 = *(const float4*)(ub1 + (size_t)n * ICC);
        const float4 q1 = *(const float4*)(ub1 + (size_t)n * ICC + 4);
        const float u0[8] = {p0.x, p0.y, p0.z, p0.w, p1.x, p1.y, p1.z, p1.w};
        const float u1[8] = {q0.x, q0.y, q0.z, q0.w, q1.x, q1.y, q1.z, q1.w};

        const char* rowp = wbuf + bsel * TILE_SMEM + r * ROWB + oq * 16;
        float4 a0 = make_float4(0.f,0.f,0.f,0.f);
        float4 a1 = make_float4(0.f,0.f,0.f,0.f);
        #pragma unroll
        for (int i = 0; i < ICC; i++) {
            const float4 wv = *(const float4*)(rowp + i * 64);   // dense, conflict-free
            a0.x = fmaf(wv.x, u0[i], a0.x); a0.y = fmaf(wv.y, u0[i], a0.y);
            a0.z = fmaf(wv.z, u0[i], a0.z); a0.w = fmaf(wv.w, u0[i], a0.w);
            a1.x = fmaf(wv.x, u1[i], a1.x); a1.y = fmaf(wv.y, u1[i], a1.y);
            a1.z = fmaf(wv.z, u1[i], a1.z); a1.w = fmaf(wv.w, u1[i], a1.w);
        }
        uh[0][tile] = a0; uh[1][tile] = a1;
        s0.x += a0.x; s0.y += a0.y; s0.z += a0.z; s0.w += a0.w;
        s1.x += a1.x; s1.y += a1.y; s1.z += a1.z; s1.w += a1.w;

        __syncthreads();                                // all local reads of buf done
        if (t == 0) {
            if (tile <= TILES - 3) {                    // consumers of this buf signal
                #pragma unroll
                for (uint32_t peer = 0; peer < CSZ; peer++)
                    mbar_arrive_cluster(emptyA[bsel], peer);
            }
            if (tile + 2 < TILES) {                     // refill this buf with tile+2
                mbar_wait(emptyA[bsel], (tile >> 1) & 1);   // whole cluster consumed
                mbar_expect_tx(fullA[bsel], TILE_GB);
                issue_tile(Wk, tile + 2, wb + bsel * TILE_SMEM, fullA[bsel], rank);
            }
        }
    }

    // iter-0 (uniform c) reduction
    {
        const float sa[8] = {s0.x, s0.y, s0.z, s0.w, s1.x, s1.y, s1.z, s1.w};
        int L; const float sv = reduce8q(sa, lane, &L);
        store_sred(&sm, w, oq, L, sv);
    }
    __syncthreads();
    squash_stage(&sm, t, /*uniform=*/true, /*first=*/true, /*writeOut=*/false, out, k, b0);

    // ---- Iterations 1,2: p = uh . vsum (b_ij linear in uh -> no logit storage) ----
    #pragma unroll 1
    for (int iter = 1; iter < 3; iter++) {
        const float4 v0 = *(const float4*)&sm.vsum[0][4 * oq];
        const float4 v1 = *(const float4*)&sm.vsum[1][4 * oq];
        float4 sc0 = make_float4(0.f,0.f,0.f,0.f), sc1 = make_float4(0.f,0.f,0.f,0.f);
        float z0 = 0.f, z1 = 0.f;
        #pragma unroll
        for (int j = 0; j < TILES; j++) {
            const float4 h0 = uh[0][j], h1 = uh[1][j];
            float pa = h0.x * v0.x;
            pa = fmaf(h0.y, v0.y, pa); pa = fmaf(h0.z, v0.z, pa); pa = fmaf(h0.w, v0.w, pa);
            float pb = h1.x * v1.x;
            pb = fmaf(h1.y, v1.y, pb); pb = fmaf(h1.z, v1.z, pb); pb = fmaf(h1.w, v1.w, pb);
            pa += __shfl_xor_sync(0xffffffffu, pa, 1);
            pb += __shfl_xor_sync(0xffffffffu, pb, 1);
            pa += __shfl_xor_sync(0xffffffffu, pa, 2);
            pb += __shfl_xor_sync(0xffffffffu, pb, 2);
            const float c0 = __expf(pa);    // softmax shift-invariant; |p| << 88
            const float c1 = __expf(pb);
            z0 += c0; z1 += c1;
            sc0.x = fmaf(c0, h0.x, sc0.x); sc0.y = fmaf(c0, h0.y, sc0.y);
            sc0.z = fmaf(c0, h0.z, sc0.z); sc0.w = fmaf(c0, h0.w, sc0.w);
            sc1.x = fmaf(c1, h1.x, sc1.x); sc1.y = fmaf(c1, h1.y, sc1.y);
            sc1.z = fmaf(c1, h1.z, sc1.z); sc1.w = fmaf(c1, h1.w, sc1.w);
        }
        const float sa[8] = {sc0.x, sc0.y, sc0.z, sc0.w, sc1.x, sc1.y, sc1.z, sc1.w};
        int L; const float sv = reduce8q(sa, lane, &L);
        store_sred(&sm, w, oq, L, sv);
        store_zred(&sm, w, lane, z0, z1);
        __syncthreads();

        squash_stage(&sm, t, /*uniform=*/false, /*first=*/false,
                     /*writeOut=*/(iter == 2), out, k, b0);
    }

    cluster_sync_();   // no CTA exits while peers' multicasts may target its SMEM
}

extern "C" void kernel_launch(void* const* d_in, const int* in_sizes, int n_in,
                              void* d_out, int out_size) {
    const float* u = (const float*)d_in[0];   // [256, 1152, 8]
    const float* W = (const float*)d_in[1];   // [10, 1152, 8, 16]
    float* out = (float*)d_out;               // [10, 256, 1, 1, 16]

    cudaFuncSetAttribute(caps_routing_kernel,
                         cudaFuncAttributeMaxDynamicSharedMemorySize, 2 * TILE_SMEM);
    dim3 grid(BT / BTILE, KC);                // 128 x 10; clusters of 8 along x
    caps_routing_kernel<<<grid, NTHREADS, 2 * TILE_SMEM>>>(u, W, out);
}